// round 10
// baseline (speedup 1.0000x reference)
#include <cuda_runtime.h>
#include <cuda_bf16.h>
#include <cstdint>

#define BATCH 2
#define SEQ 2048
#define DIM 512
#define INNER 512
#define N_HEAD 8
#define HEAD_DIM 64
#define ATT_T 1e-4f
#define SCALE_F 0.125f

typedef unsigned long long ull;
typedef unsigned u32;

__device__ float g_Q[BATCH * SEQ * INNER];
__device__ float g_K[BATCH * SEQ * INNER];
__device__ float g_V[BATCH * SEQ * INNER];
__device__ float g_O[BATCH * SEQ * INNER];
__device__ float g_P[(size_t)BATCH * N_HEAD * SEQ * SEQ];
__device__ float g_Z[BATCH * N_HEAD * SEQ];
__device__ __nv_bfloat16 g_Vth[BATCH * N_HEAD * 16 * 8192];
__device__ __nv_bfloat16 g_Vtl[BATCH * N_HEAD * 16 * 8192];

// ---------------- f32x2 helpers (scalar gemm) ----------------------------
static __device__ __forceinline__ void fma2(ull& d, ull a, ull b) {
    asm("fma.rn.f32x2 %0, %1, %2, %0;" : "+l"(d) : "l"(a), "l"(b));
}
static __device__ __forceinline__ float psum(ull v) {
    u32 lo, hi;
    asm("mov.b64 {%0, %1}, %2;" : "=r"(lo), "=r"(hi) : "l"(v));
    return __uint_as_float(lo) + __uint_as_float(hi);
}
static __device__ __forceinline__ void st_sw4(float* base, int stride_f,
                                              int row, int c, int t, float4 v) {
    int e = ((c >> 1) ^ t) & ~1;
    if (t & 1) { float x = v.x, y = v.y; v.x = v.z; v.y = v.w; v.z = x; v.w = y; }
    *(float4*)&base[row * stride_f + (e << 1)] = v;
}

// ---------------- mma.sync helpers (sm_80+ PTX, compiles for sm_103) ------
static __device__ __forceinline__ u32 su32(const void* p) {
    u32 a;
    asm("{ .reg .u64 t; cvta.to.shared.u64 t, %1; cvt.u32.u64 %0, t; }" : "=r"(a) : "l"(p));
    return a;
}
static __device__ __forceinline__ void mma_bf16(float* d, const u32* a, const u32* b) {
    asm volatile(
        "mma.sync.aligned.m16n8k16.row.col.f32.bf16.bf16.f32 "
        "{%0,%1,%2,%3}, {%4,%5,%6,%7}, {%8,%9}, {%0,%1,%2,%3};"
        : "+f"(d[0]), "+f"(d[1]), "+f"(d[2]), "+f"(d[3])
        : "r"(a[0]), "r"(a[1]), "r"(a[2]), "r"(a[3]), "r"(b[0]), "r"(b[1]));
}
static __device__ __forceinline__ void ldsm4(u32* r, u32 addr) {
    asm volatile("ldmatrix.sync.aligned.m8n8.x4.shared.b16 {%0,%1,%2,%3}, [%4];"
                 : "=r"(r[0]), "=r"(r[1]), "=r"(r[2]), "=r"(r[3]) : "r"(addr));
}
static __device__ __forceinline__ void ldsm2(u32* r, u32 addr) {
    asm volatile("ldmatrix.sync.aligned.m8n8.x2.shared.b16 {%0,%1}, [%2];"
                 : "=r"(r[0]), "=r"(r[1]) : "r"(addr));
}
static __device__ __forceinline__ u32 pkb(float a, float b) {
    __nv_bfloat162 t = __floats2bfloat162_rn(a, b);
    return *reinterpret_cast<u32*>(&t);
}
static __device__ __forceinline__ void spl(float x, float& h, float& l) {
    h = __bfloat162float(__float2bfloat16(x));
    l = x - h;
}

// fill a [128 x 64] fp32 tile (row stride INNER) -> bf16 hi/lo, 128B rows,
// XOR-swizzled for ldmatrix
static __device__ __forceinline__ void fillQK(char* dh, char* dl,
                                              const float* src, int tid, float scale)
{
    #pragma unroll
    for (int i = 0; i < 8; i++) {
        int idx = tid + 256 * i, row = idx >> 4, c = (idx & 15) << 2;
        float4 v = *(const float4*)&src[(size_t)row * INNER + c];
        v.x *= scale; v.y *= scale; v.z *= scale; v.w *= scale;
        float h0, l0, h1, l1, h2, l2, h3, l3;
        spl(v.x, h0, l0); spl(v.y, h1, l1); spl(v.z, h2, l2); spl(v.w, h3, l3);
        u32 off = (u32)(row * 128 + c * 2) ^ ((u32)(row & 7) << 4);
        *(uint2*)(dh + off) = make_uint2(pkb(h0, h1), pkb(h2, h3));
        *(uint2*)(dl + off) = make_uint2(pkb(l0, l1), pkb(l2, l3));
    }
}

// ---------------------------------------------------------------------------
// scalar FFMA2 gemm128 (projections + output proj) — proven
// ---------------------------------------------------------------------------
__global__ void __launch_bounds__(512, 1) gemm128(
    const float* __restrict__ A, const float* __restrict__ B,
    const float* __restrict__ bias, float* __restrict__ C, int M, int N, int K)
{
    extern __shared__ float sm[];
    float* As = sm;
    float* Bs = sm + 128 * 64;
    const int tid = threadIdx.x, tx = tid & 31, ty = tid >> 5;
    const int tx4 = tx << 2, ty8 = ty << 3;
    const int bn = blockIdx.x * 128, bm = blockIdx.y * 128;

    ull acc2[8][4];
    #pragma unroll
    for (int i = 0; i < 8; i++)
        #pragma unroll
        for (int j = 0; j < 4; j++) acc2[i][j] = 0ull;

    for (int kc = 0; kc < K; kc += 64) {
        __syncthreads();
        #pragma unroll
        for (int i = 0; i < 4; i++) {
            int idx = tid + 512 * i, row = idx >> 4, c = (idx & 15) << 2;
            float4 v = *(const float4*)&A[(size_t)(bm + row) * K + kc + c];
            st_sw4(As, 64, row, c, row >> 3, v);
        }
        #pragma unroll
        for (int i = 0; i < 4; i++) {
            int idx = tid + 512 * i, k = idx >> 5, c = (idx & 31) << 2;
            float4 v = *(const float4*)&B[(size_t)(kc + k) * N + bn + c];
            int t = c >> 2, pk = k >> 1, sl = ((pk ^ t) << 1) | (k & 1);
            Bs[(c + 0) * 64 + sl] = v.x; Bs[(c + 1) * 64 + sl] = v.y;
            Bs[(c + 2) * 64 + sl] = v.z; Bs[(c + 3) * 64 + sl] = v.w;
        }
        __syncthreads();
        #pragma unroll 4
        for (int dp = 0; dp < 32; dp++) {
            ull a2[8], b2[4];
            int ao = (dp ^ ty) << 1, bo = (dp ^ tx) << 1;
            #pragma unroll
            for (int i = 0; i < 8; i++) a2[i] = *(const ull*)&As[(ty8 + i) * 64 + ao];
            #pragma unroll
            for (int j = 0; j < 4; j++) b2[j] = *(const ull*)&Bs[(tx4 + j) * 64 + bo];
            #pragma unroll
            for (int i = 0; i < 8; i++)
                #pragma unroll
                for (int j = 0; j < 4; j++) fma2(acc2[i][j], a2[i], b2[j]);
        }
    }
    #pragma unroll
    for (int i = 0; i < 8; i++) {
        int row = bm + ty8 + i, col = bn + tx4;
        float4 o = {psum(acc2[i][0]), psum(acc2[i][1]), psum(acc2[i][2]), psum(acc2[i][3])};
        if (bias) { o.x += bias[col]; o.y += bias[col+1]; o.z += bias[col+2]; o.w += bias[col+3]; }
        *(float4*)&C[(size_t)row * N + col] = o;
    }
}

// ---------------------------------------------------------------------------
// convert V -> V^T bf16 hi/lo tiles [64 d][128 k], 256B rows, swizzled, gmem
// ---------------------------------------------------------------------------
__global__ void __launch_bounds__(256) convert_vt()
{
    __shared__ __align__(128) char sh[16384];
    __shared__ __align__(128) char sl_[16384];
    const int tid = threadIdx.x;
    const int t = blockIdx.x, h = blockIdx.y, b = blockIdx.z;
    const size_t base = ((size_t)b * SEQ + t * 128) * INNER + h * HEAD_DIM;

    #pragma unroll
    for (int i = 0; i < 8; i++) {
        int idx = tid + 256 * i, k = idx >> 4, d4 = (idx & 15) << 2;
        float4 v = *(const float4*)&g_V[base + (size_t)k * INNER + d4];
        float vv[4] = {v.x, v.y, v.z, v.w};
        #pragma unroll
        for (int j = 0; j < 4; j++) {
            int d = d4 + j;
            float hi, lo; spl(vv[j], hi, lo);
            u32 off = (u32)(d * 256 + k * 2) ^ ((u32)(d & 7) << 4);
            *(__nv_bfloat16*)(sh + off) = __float2bfloat16(hi);
            *(__nv_bfloat16*)(sl_ + off) = __float2bfloat16(lo);
        }
    }
    __syncthreads();
    size_t tb = (((size_t)b * N_HEAD + h) * 16 + t) * 8192;
    #pragma unroll
    for (int i = 0; i < 4; i++) {
        ((uint4*)&g_Vth[tb])[tid + 256 * i] = ((const uint4*)sh)[tid + 256 * i];
        ((uint4*)&g_Vtl[tb])[tid + 256 * i] = ((const uint4*)sl_)[tid + 256 * i];
    }
}

// ---------------------------------------------------------------------------
// attn_score_mma: P = exp(QK^T*scale) -> g_P, Z row sums. HMMA split-bf16.
// 256 thr = 8 warps (4m x 2n); warp tile 32q x 64k.
// ---------------------------------------------------------------------------
#define AS_QH 0
#define AS_QL 16384
#define AS_K(buf) (32768 + (buf) * 32768)
#define AS_ZP 98304
#define AS_SZ (98304 + 1024 + 1024)

__global__ void __launch_bounds__(256, 1) attn_score_mma()
{
    extern __shared__ char smraw[];
    char* smb = (char*)(((uintptr_t)smraw + 1023) & ~(uintptr_t)1023);
    float* zp = (float*)(smb + AS_ZP);
    const u32 sb = su32(smb);
    const int tid = threadIdx.x, lane = tid & 31, wid = tid >> 5;
    const int wm = wid & 3, wn = wid >> 2;
    const int g = lane >> 2, t = lane & 3;
    const int qt = blockIdx.x, h = blockIdx.y, b = blockIdx.z;
    const size_t baseQ = ((size_t)b * SEQ + qt * 128) * INNER + h * HEAD_DIM;
    const size_t baseK = ((size_t)b * SEQ) * INNER + h * HEAD_DIM;
    const size_t rowP = ((size_t)(b * N_HEAD + h) * SEQ + qt * 128);

    fillQK(smb + AS_QH, smb + AS_QL, &g_Q[baseQ], tid, SCALE_F);
    fillQK(smb + AS_K(0), smb + AS_K(0) + 16384, &g_K[baseK], tid, 1.f);

    const int arow = lane & 15;
    const int acolb = (lane & 16) ? 16 : 0;
    const int brow = lane & 7;
    const int bcolb = (lane & 8) ? 16 : 0;

    float zacc[4] = {0.f, 0.f, 0.f, 0.f};

    for (int kt = 0; kt < 16; kt++) {
        const int buf = kt & 1;
        __syncthreads();

        float acc[2][8][4];
        #pragma unroll
        for (int mi = 0; mi < 2; mi++)
            #pragma unroll
            for (int ni = 0; ni < 8; ni++)
                #pragma unroll
                for (int c = 0; c < 4; c++) acc[mi][ni][c] = 0.f;

        const u32 kbh = sb + AS_K(buf), kbl = kbh + 16384;
        #pragma unroll
        for (int ks = 0; ks < 4; ks++) {
            const int kkb = ks * 32;
            u32 ah[2][4], al[2][4];
            #pragma unroll
            for (int mi = 0; mi < 2; mi++) {
                int r = wm * 32 + mi * 16 + arow;
                u32 off = ((u32)(r * 128 + kkb + acolb)) ^ ((u32)(r & 7) << 4);
                ldsm4(ah[mi], sb + AS_QH + off);
                ldsm4(al[mi], sb + AS_QL + off);
            }
            u32 bh[8][2], bl[8][2];
            #pragma unroll
            for (int ni = 0; ni < 8; ni++) {
                int r = wn * 64 + ni * 8 + brow;
                u32 off = ((u32)(r * 128 + kkb + bcolb)) ^ ((u32)(r & 7) << 4);
                ldsm2(bh[ni], kbh + off);
                ldsm2(bl[ni], kbl + off);
            }
            #pragma unroll
            for (int mi = 0; mi < 2; mi++)
                #pragma unroll
                for (int ni = 0; ni < 8; ni++) {
                    mma_bf16(acc[mi][ni], ah[mi], bh[ni]);
                    mma_bf16(acc[mi][ni], ah[mi], bl[ni]);
                    mma_bf16(acc[mi][ni], al[mi], bh[ni]);
                }
        }

        if (kt < 15)
            fillQK(smb + AS_K(buf ^ 1), smb + AS_K(buf ^ 1) + 16384,
                   &g_K[baseK + (size_t)(kt + 1) * 128 * INNER], tid, 1.f);

        #pragma unroll
        for (int mi = 0; mi < 2; mi++) {
            size_t r0 = rowP + wm * 32 + mi * 16 + g;
            #pragma unroll
            for (int ni = 0; ni < 8; ni++) {
                float p0 = __expf(acc[mi][ni][0]);
                float p1 = __expf(acc[mi][ni][1]);
                float p2 = __expf(acc[mi][ni][2]);
                float p3 = __expf(acc[mi][ni][3]);
                zacc[mi * 2 + 0] += p0 + p1;
                zacc[mi * 2 + 1] += p2 + p3;
                int col = kt * 128 + wn * 64 + ni * 8 + t * 2;
                *(float2*)&g_P[r0 * SEQ + col] = make_float2(p0, p1);
                *(float2*)&g_P[(r0 + 8) * SEQ + col] = make_float2(p2, p3);
            }
        }
    }

    #pragma unroll
    for (int i = 0; i < 4; i++) {
        zacc[i] += __shfl_xor_sync(0xffffffffu, zacc[i], 1);
        zacc[i] += __shfl_xor_sync(0xffffffffu, zacc[i], 2);
    }
    if (t == 0) {
        #pragma unroll
        for (int mi = 0; mi < 2; mi++)
            #pragma unroll
            for (int hf = 0; hf < 2; hf++)
                zp[wn * 128 + wm * 32 + mi * 16 + hf * 8 + g] = zacc[mi * 2 + hf];
    }
    __syncthreads();
    if (tid < 128)
        g_Z[(b * N_HEAD + h) * SEQ + qt * 128 + tid] = zp[tid] + zp[128 + tid];
}

// ---------------------------------------------------------------------------
// attn_pv_mma: O = (relu(P - t*Z) @ V) / rowsum. HMMA split-bf16.
// 256 thr = 8 warps (4m x 2n); warp tile 32q x 32d.
// ---------------------------------------------------------------------------
#define PV_W(buf) ((buf) * 65536)
#define PV_V(buf) (131072 + (buf) * 32768)
#define PV_WS 196608
#define PV_TH 197120
#define PV_SZ (197632 + 1024)

__global__ void __launch_bounds__(256, 1) attn_pv_mma()
{
    extern __shared__ char smraw[];
    char* smb = (char*)(((uintptr_t)smraw + 1023) & ~(uintptr_t)1023);
    float* wsumS = (float*)(smb + PV_WS);
    float* thrS = (float*)(smb + PV_TH);
    const u32 sb = su32(smb);
    const int tid = threadIdx.x, lane = tid & 31, wid = tid >> 5;
    const int wm = wid & 3, wn = wid >> 2;
    const int g = lane >> 2, t = lane & 3;
    const int qt = blockIdx.x, h = blockIdx.y, b = blockIdx.z;
    const size_t rowP = ((size_t)(b * N_HEAD + h) * SEQ + qt * 128);
    const int rowZ = (b * N_HEAD + h) * SEQ + qt * 128;
    const size_t baseO = ((size_t)b * SEQ + qt * 128) * INNER + h * HEAD_DIM;
    const size_t tbV = (((size_t)b * N_HEAD + h) * 16) * 8192;

    if (tid < 128) { thrS[tid] = ATT_T * g_Z[rowZ + tid]; wsumS[tid] = 0.f; }
    __syncthreads();

    const int arow = lane & 15;
    const int acolb = (lane & 16) ? 16 : 0;
    const int brow = lane & 7;
    const int bcolb = (lane & 8) ? 16 : 0;

    // W/V fill lambdas (inline macro-style)
    auto fillW = [&](int buf, int kt) {
        char* wh = smb + PV_W(buf);
        char* wl = wh + 32768;
        #pragma unroll
        for (int i = 0; i < 16; i++) {
            int idx = tid + 256 * i, row = idx >> 5, k4 = (idx & 31) << 2;
            float4 p = *(const float4*)&g_P[(rowP + row) * SEQ + kt * 128 + k4];
            float th = thrS[row];
            float w0 = fmaxf(p.x - th, 0.f), w1 = fmaxf(p.y - th, 0.f);
            float w2 = fmaxf(p.z - th, 0.f), w3 = fmaxf(p.w - th, 0.f);
            float h0, l0, h1, l1, h2, l2, h3, l3;
            spl(w0, h0, l0); spl(w1, h1, l1); spl(w2, h2, l2); spl(w3, h3, l3);
            u32 off = ((u32)(row * 256 + k4 * 2)) ^ ((u32)(row & 7) << 4);
            *(uint2*)(wh + off) = make_uint2(pkb(h0, h1), pkb(h2, h3));
            *(uint2*)(wl + off) = make_uint2(pkb(l0, l1), pkb(l2, l3));
            float s = (w0 + w1) + (w2 + w3);
            #pragma unroll
            for (int o = 16; o > 0; o >>= 1) s += __shfl_xor_sync(0xffffffffu, s, o);
            if (lane == 0) wsumS[row] += s;
        }
    };
    auto fillV = [&](int buf, int kt) {
        const uint4* sH = (const uint4*)&g_Vth[tbV + (size_t)kt * 8192];
        const uint4* sL = (const uint4*)&g_Vtl[tbV + (size_t)kt * 8192];
        uint4* dH = (uint4*)(smb + PV_V(buf));
        uint4* dL = (uint4*)(smb + PV_V(buf) + 16384);
        #pragma unroll
        for (int i = 0; i < 4; i++) {
            dH[tid + 256 * i] = sH[tid + 256 * i];
            dL[tid + 256 * i] = sL[tid + 256 * i];
        }
    };

    fillW(0, 0);
    fillV(0, 0);

    float acc[2][4][4];
    #pragma unroll
    for (int mi = 0; mi < 2; mi++)
        #pragma unroll
        for (int ni = 0; ni < 4; ni++)
            #pragma unroll
            for (int c = 0; c < 4; c++) acc[mi][ni][c] = 0.f;

    for (int kt = 0; kt < 16; kt++) {
        const int buf = kt & 1;
        __syncthreads();

        const u32 wbh = sb + PV_W(buf), wbl = wbh + 32768;
        const u32 vbh = sb + PV_V(buf), vbl = vbh + 16384;
        #pragma unroll
        for (int ks = 0; ks < 8; ks++) {
            const int kkb = ks * 32;
            u32 ah[2][4], al[2][4];
            #pragma unroll
            for (int mi = 0; mi < 2; mi++) {
                int r = wm * 32 + mi * 16 + arow;
                u32 off = ((u32)(r * 256 + kkb + acolb)) ^ ((u32)(r & 7) << 4);
                ldsm4(ah[mi], wbh + off);
                ldsm4(al[mi], wbl + off);
            }
            u32 bh[4][2], bl[4][2];
            #pragma unroll
            for (int ni = 0; ni < 4; ni++) {
                int r = wn * 32 + ni * 8 + brow;
                u32 off = ((u32)(r * 256 + kkb + bcolb)) ^ ((u32)(r & 7) << 4);
                ldsm2(bh[ni], vbh + off);
                ldsm2(bl[ni], vbl + off);
            }
            #pragma unroll
            for (int mi = 0; mi < 2; mi++)
                #pragma unroll
                for (int ni = 0; ni < 4; ni++) {
                    mma_bf16(acc[mi][ni], ah[mi], bh[ni]);
                    mma_bf16(acc[mi][ni], ah[mi], bl[ni]);
                    mma_bf16(acc[mi][ni], al[mi], bh[ni]);
                }
        }

        if (kt < 15) {
            fillW(buf ^ 1, kt + 1);
            fillV(buf ^ 1, kt + 1);
        }
    }

    __syncthreads();
    #pragma unroll
    for (int mi = 0; mi < 2; mi++) {
        int r0 = wm * 32 + mi * 16 + g;
        float i0 = 1.f / wsumS[r0], i1 = 1.f / wsumS[r0 + 8];
        #pragma unroll
        for (int ni = 0; ni < 4; ni++) {
            int col = wn * 32 + ni * 8 + t * 2;
            *(float2*)&g_O[baseO + (size_t)r0 * INNER + col] =
                make_float2(acc[mi][ni][0] * i0, acc[mi][ni][1] * i0);
            *(float2*)&g_O[baseO + (size_t)(r0 + 8) * INNER + col] =
                make_float2(acc[mi][ni][2] * i1, acc[mi][ni][3] * i1);
        }
    }
}

// ---------------------------------------------------------------------------
extern "C" void kernel_launch(void* const* d_in, const int* in_sizes, int n_in,
                              void* d_out, int out_size)
{
    const float* fr = (const float*)d_in[0];
    const float* dt = (const float*)d_in[1];
    const float* Wq = (const float*)d_in[2];
    const float* Wk = (const float*)d_in[3];
    const float* Wv = (const float*)d_in[4];
    const float* Wo = (const float*)d_in[5];
    const float* bo = (const float*)d_in[6];
    float* out = (float*)d_out;

    float *pQ, *pK, *pV, *pO;
    cudaGetSymbolAddress((void**)&pQ, g_Q);
    cudaGetSymbolAddress((void**)&pK, g_K);
    cudaGetSymbolAddress((void**)&pV, g_V);
    cudaGetSymbolAddress((void**)&pO, g_O);

    const int M = BATCH * SEQ;
    const int smG = 128 * 64 * 2 * (int)sizeof(float);
    cudaFuncSetAttribute(gemm128, cudaFuncAttributeMaxDynamicSharedMemorySize, smG);
    cudaFuncSetAttribute(attn_score_mma, cudaFuncAttributeMaxDynamicSharedMemorySize, AS_SZ);
    cudaFuncSetAttribute(attn_pv_mma, cudaFuncAttributeMaxDynamicSharedMemorySize, PV_SZ);

    dim3 gp(INNER / 128, M / 128);
    gemm128<<<gp, 512, smG>>>(fr, Wq, nullptr, pQ, M, INNER, DIM);
    gemm128<<<gp, 512, smG>>>(dt, Wk, nullptr, pK, M, INNER, DIM);
    gemm128<<<gp, 512, smG>>>(dt, Wv, nullptr, pV, M, INNER, DIM);

    convert_vt<<<dim3(16, N_HEAD, BATCH), 256>>>();
    attn_score_mma<<<dim3(16, N_HEAD, BATCH), 256, AS_SZ>>>();
    attn_pv_mma<<<dim3(16, N_HEAD, BATCH), 256, PV_SZ>>>();

    dim3 go(DIM / 128, M / 128);
    gemm128<<<go, 512, smG>>>(pO, Wo, bo, out, M, DIM, INNER);
}

// round 12
// speedup vs baseline: 1.1691x; 1.1691x over previous
#include <cuda_runtime.h>
#include <cstdint>

#define BATCH 2
#define SEQ 2048
#define DIM 512
#define INNER 512
#define N_HEAD 8
#define HEAD_DIM 64
#define ATT_T 1e-4f
#define SCALE_F 0.125f

typedef unsigned long long ull;
typedef unsigned u32;

// scratch (allocation-free rule: __device__ globals)
__device__ float g_Q[BATCH * SEQ * INNER];
__device__ float g_K[BATCH * SEQ * INNER];
__device__ float g_V[BATCH * SEQ * INNER];
__device__ float g_O[BATCH * SEQ * INNER];
__device__ float g_P[(size_t)BATCH * N_HEAD * SEQ * SEQ];   // exp(scores)
__device__ float g_Z[BATCH * N_HEAD * SEQ];

// ---------------- packed f32x2 helpers ---------------------------------
static __device__ __forceinline__ void fma2(ull& d, ull a, ull b) {
    asm("fma.rn.f32x2 %0, %1, %2, %0;" : "+l"(d) : "l"(a), "l"(b));
}
static __device__ __forceinline__ float psum(ull v) {
    u32 lo, hi;
    asm("mov.b64 {%0, %1}, %2;" : "=r"(lo), "=r"(hi) : "l"(v));
    return __uint_as_float(lo) + __uint_as_float(hi);
}
// swizzled float4 store: logical pair p=c>>1 -> physical slot p^t
static __device__ __forceinline__ void st_sw4(float* base, int stride_f,
                                              int row, int c, int t, float4 v) {
    int e = ((c >> 1) ^ t) & ~1;
    if (t & 1) { float x = v.x, y = v.y; v.x = v.z; v.y = v.w; v.z = x; v.w = y; }
    *(float4*)&base[row * stride_f + (e << 1)] = v;
}

// ---------------------------------------------------------------------------
// gemm128: C[M,N] = A[M,K] @ B[K,N] (+bias). 512 thr, 128x128 tile, BK=64.
// ---------------------------------------------------------------------------
__global__ void __launch_bounds__(512, 1) gemm128(
    const float* __restrict__ A, const float* __restrict__ B,
    const float* __restrict__ bias, float* __restrict__ C, int M, int N, int K)
{
    extern __shared__ float sm[];
    float* As = sm;              // 128 x 64
    float* Bs = sm + 128 * 64;   // 128 x 64 (B transposed)
    const int tid = threadIdx.x, tx = tid & 31, ty = tid >> 5;
    const int tx4 = tx << 2, ty8 = ty << 3;
    const int bn = blockIdx.x * 128, bm = blockIdx.y * 128;

    ull acc2[8][4];
    #pragma unroll
    for (int i = 0; i < 8; i++)
        #pragma unroll
        for (int j = 0; j < 4; j++) acc2[i][j] = 0ull;

    for (int kc = 0; kc < K; kc += 64) {
        __syncthreads();
        #pragma unroll
        for (int i = 0; i < 4; i++) {
            int idx = tid + 512 * i, row = idx >> 4, c = (idx & 15) << 2;
            float4 v = *(const float4*)&A[(size_t)(bm + row) * K + kc + c];
            st_sw4(As, 64, row, c, row >> 3, v);
        }
        #pragma unroll
        for (int i = 0; i < 4; i++) {
            int idx = tid + 512 * i, k = idx >> 5, c = (idx & 31) << 2;
            float4 v = *(const float4*)&B[(size_t)(kc + k) * N + bn + c];
            int t = c >> 2, pk = k >> 1, sl = ((pk ^ t) << 1) | (k & 1);
            Bs[(c + 0) * 64 + sl] = v.x; Bs[(c + 1) * 64 + sl] = v.y;
            Bs[(c + 2) * 64 + sl] = v.z; Bs[(c + 3) * 64 + sl] = v.w;
        }
        __syncthreads();
        #pragma unroll 4
        for (int dp = 0; dp < 32; dp++) {
            ull a2[8], b2[4];
            int ao = (dp ^ ty) << 1, bo = (dp ^ tx) << 1;
            #pragma unroll
            for (int i = 0; i < 8; i++) a2[i] = *(const ull*)&As[(ty8 + i) * 64 + ao];
            #pragma unroll
            for (int j = 0; j < 4; j++) b2[j] = *(const ull*)&Bs[(tx4 + j) * 64 + bo];
            #pragma unroll
            for (int i = 0; i < 8; i++)
                #pragma unroll
                for (int j = 0; j < 4; j++) fma2(acc2[i][j], a2[i], b2[j]);
        }
    }
    #pragma unroll
    for (int i = 0; i < 8; i++) {
        int row = bm + ty8 + i, col = bn + tx4;
        float4 o = {psum(acc2[i][0]), psum(acc2[i][1]), psum(acc2[i][2]), psum(acc2[i][3])};
        if (bias) { o.x += bias[col]; o.y += bias[col+1]; o.z += bias[col+2]; o.w += bias[col+3]; }
        *(float4*)&C[(size_t)row * N + col] = o;
    }
}

// ---------------------------------------------------------------------------
// Pass A: P = exp(QK^T*scale) -> g_P, Z = row sums.  256 thr = 16(ty) x 16(tx),
// 8x8 micro-tile (crossbar-balanced), K double-buffered (one sync/iter).
// Q pre-scaled by SCALE_F (exact, power of 2). smem: Qs + K0 + K1 = 96KB.
// ---------------------------------------------------------------------------
static __device__ __forceinline__ void fill_tile_sw(
    float* dst, const float* src, int tid, float scale)
{
    #pragma unroll
    for (int i = 0; i < 8; i++) {
        int idx = tid + 256 * i, row = idx >> 4, c = (idx & 15) << 2;
        float4 v = *(const float4*)&src[(size_t)row * INNER + c];
        v.x *= scale; v.y *= scale; v.z *= scale; v.w *= scale;
        st_sw4(dst, 64, row, c, row >> 3, v);
    }
}

__global__ void __launch_bounds__(256, 1) attn_score()
{
    extern __shared__ float sm[];
    float* Qs = sm;                                   // 128 x 64
    float* Kb0 = sm + 8192;                           // 128 x 64
    float* Kb1 = sm + 16384;                          // 128 x 64

    const int tid = threadIdx.x;
    const int tx = tid & 15, ty = tid >> 4;
    const int tx8 = tx << 3, ty8 = ty << 3;
    const int qt = blockIdx.x, h = blockIdx.y, b = blockIdx.z;

    const size_t baseQ = ((size_t)b * SEQ + qt * 128) * INNER + h * HEAD_DIM;
    const size_t baseK = ((size_t)b * SEQ) * INNER + h * HEAD_DIM;
    const size_t rowP = ((size_t)(b * N_HEAD + h) * SEQ + qt * 128);

    fill_tile_sw(Qs, &g_Q[baseQ], tid, SCALE_F);
    fill_tile_sw(Kb0, &g_K[baseK], tid, 1.f);

    float l[8];
    #pragma unroll
    for (int i = 0; i < 8; i++) l[i] = 0.f;

    for (int kt = 0; kt < 16; kt++) {
        __syncthreads();
        const float* Ks = (kt & 1) ? Kb1 : Kb0;

        ull acc2[8][8];
        #pragma unroll
        for (int i = 0; i < 8; i++)
            #pragma unroll
            for (int j = 0; j < 8; j++) acc2[i][j] = 0ull;

        #pragma unroll 4
        for (int dp = 0; dp < 32; dp++) {
            ull q2[8], k2[8];
            int qo = (dp ^ ty) << 1;
            int ko = (dp ^ tx) << 1;
            #pragma unroll
            for (int i = 0; i < 8; i++) q2[i] = *(const ull*)&Qs[(ty8 + i) * 64 + qo];
            #pragma unroll
            for (int j = 0; j < 8; j++) k2[j] = *(const ull*)&Ks[(tx8 + j) * 64 + ko];
            #pragma unroll
            for (int i = 0; i < 8; i++)
                #pragma unroll
                for (int j = 0; j < 8; j++) fma2(acc2[i][j], q2[i], k2[j]);
        }

        // prefetch next K into the other buffer (overlaps epilogue)
        if (kt < 15)
            fill_tile_sw((kt & 1) ? Kb0 : Kb1,
                         &g_K[baseK + (size_t)(kt + 1) * 128 * INNER], tid, 1.f);

        // epilogue: exp + coalesced store + Z accumulation
        #pragma unroll
        for (int qi = 0; qi < 8; qi++) {
            float p[8];
            #pragma unroll
            for (int j = 0; j < 8; j++) p[j] = __expf(psum(acc2[qi][j]));
            l[qi] += ((p[0] + p[1]) + (p[2] + p[3])) + ((p[4] + p[5]) + (p[6] + p[7]));
            size_t ro = (rowP + ty8 + qi) * SEQ + kt * 128 + tx8;
            *(float4*)&g_P[ro] = make_float4(p[0], p[1], p[2], p[3]);
            *(float4*)&g_P[ro + 4] = make_float4(p[4], p[5], p[6], p[7]);
        }
    }

    #pragma unroll
    for (int qi = 0; qi < 8; qi++) {
        float v = l[qi];
        #pragma unroll
        for (int o = 1; o < 16; o <<= 1)
            v += __shfl_xor_sync(0xffffffffu, v, o);
        if (tx == 0)
            g_Z[(b * N_HEAD + h) * SEQ + qt * 128 + ty8 + qi] = v;
    }
}

// ---------------------------------------------------------------------------
// Pass B: w = relu(P - t*Z), O = (w @ V) / rowsum(w).
// 256 thr = 16x16, 8q x 4d. Deferred wsum (register wpart[16], single
// end-of-kernel reduction) -> no per-iter shuffle chains, LDGs can batch.
// ---------------------------------------------------------------------------
__global__ void __launch_bounds__(256, 2) attn_pv()
{
    extern __shared__ float sm[];
    float* Ws = sm;                    // 128 x 128, tag q>>3
    float* Vs = Ws + 128 * 128;        // 64 x 128 (V^T), tag d>>2
    float* wsumS = Vs + 64 * 128;      // 128
    float* thrS  = wsumS + 128;        // 128

    const int tid = threadIdx.x;
    const int tx = tid & 15, ty = tid >> 4;
    const int wid = tid >> 5, lane = tid & 31;
    const int tx4 = tx << 2, ty8 = ty << 3;
    const int qt = blockIdx.x, h = blockIdx.y, b = blockIdx.z;

    const size_t baseV = ((size_t)b * SEQ) * INNER + h * HEAD_DIM;
    const size_t baseO = ((size_t)b * SEQ + qt * 128) * INNER + h * HEAD_DIM;
    const size_t rowP  = ((size_t)(b * N_HEAD + h) * SEQ + qt * 128);
    const int    rowZ  = (b * N_HEAD + h) * SEQ + qt * 128;

    if (tid < 128) thrS[tid] = ATT_T * g_Z[rowZ + tid];

    float wpart[16];
    #pragma unroll
    for (int i = 0; i < 16; i++) wpart[i] = 0.f;

    ull oacc[8][4];
    #pragma unroll
    for (int i = 0; i < 8; i++)
        #pragma unroll
        for (int j = 0; j < 4; j++) oacc[i][j] = 0ull;

    for (int kt = 0; kt < 16; kt++) {
        __syncthreads();
        // fill Ws: w = relu(P - thr); per-thread row sums into wpart (row = 8i+wid)
        #pragma unroll
        for (int i = 0; i < 16; i++) {
            int idx = tid + 256 * i;
            int row = idx >> 5;                 // = 8*i + wid
            int c   = (idx & 31) << 2;
            float4 p = *(const float4*)&g_P[(rowP + row) * SEQ + kt * 128 + c];
            float t = thrS[row];
            float4 w;
            w.x = fmaxf(p.x - t, 0.f); w.y = fmaxf(p.y - t, 0.f);
            w.z = fmaxf(p.z - t, 0.f); w.w = fmaxf(p.w - t, 0.f);
            wpart[i] += (w.x + w.y) + (w.z + w.w);
            st_sw4(Ws, 128, row, c, row >> 3, w);
        }
        // fill Vs (transpose)
        #pragma unroll
        for (int i = 0; i < 8; i++) {
            int idx = tid + 256 * i;
            int row = idx >> 4;                 // k 0..127
            int c   = (idx & 15) << 2;          // d
            float4 v = *(const float4*)&g_V[baseV + (size_t)(kt * 128 + row) * INNER + c];
            int t = c >> 2, pk = row >> 1;
            int sl = ((pk ^ t) << 1) | (row & 1);
            Vs[(c + 0) * 128 + sl] = v.x; Vs[(c + 1) * 128 + sl] = v.y;
            Vs[(c + 2) * 128 + sl] = v.z; Vs[(c + 3) * 128 + sl] = v.w;
        }
        __syncthreads();

        #pragma unroll 4
        for (int kp = 0; kp < 64; kp++) {
            ull w2[8], v2[4];
            int wo = (kp ^ ty) << 1;
            int vo = (kp ^ tx) << 1;
            #pragma unroll
            for (int i = 0; i < 8; i++) w2[i] = *(const ull*)&Ws[(ty8 + i) * 128 + wo];
            #pragma unroll
            for (int j = 0; j < 4; j++) v2[j] = *(const ull*)&Vs[(tx4 + j) * 128 + vo];
            #pragma unroll
            for (int i = 0; i < 8; i++)
                #pragma unroll
                for (int j = 0; j < 4; j++) fma2(oacc[i][j], w2[i], v2[j]);
        }
    }

    // single deferred wsum reduction: wpart[i] -> wsumS[8*i + wid]
    __syncthreads();
    #pragma unroll
    for (int i = 0; i < 16; i++) {
        float s = wpart[i];
        #pragma unroll
        for (int o = 16; o > 0; o >>= 1)
            s += __shfl_xor_sync(0xffffffffu, s, o);
        if (lane == 0) wsumS[8 * i + wid] = s;
    }
    __syncthreads();

    #pragma unroll
    for (int qi = 0; qi < 8; qi++) {
        float inv = 1.f / wsumS[ty8 + qi];
        float4 ov = {psum(oacc[qi][0]) * inv, psum(oacc[qi][1]) * inv,
                     psum(oacc[qi][2]) * inv, psum(oacc[qi][3]) * inv};
        *(float4*)&g_O[baseO + (size_t)(ty8 + qi) * INNER + tx4] = ov;
    }
}

// ---------------------------------------------------------------------------
extern "C" void kernel_launch(void* const* d_in, const int* in_sizes, int n_in,
                              void* d_out, int out_size)
{
    const float* fr = (const float*)d_in[0];
    const float* dt = (const float*)d_in[1];
    const float* Wq = (const float*)d_in[2];
    const float* Wk = (const float*)d_in[3];
    const float* Wv = (const float*)d_in[4];
    const float* Wo = (const float*)d_in[5];
    const float* bo = (const float*)d_in[6];
    float* out = (float*)d_out;

    float *pQ, *pK, *pV, *pO;
    cudaGetSymbolAddress((void**)&pQ, g_Q);
    cudaGetSymbolAddress((void**)&pK, g_K);
    cudaGetSymbolAddress((void**)&pV, g_V);
    cudaGetSymbolAddress((void**)&pO, g_O);

    const int M = BATCH * SEQ;   // 4096

    const int smG = 128 * 64 * 2 * (int)sizeof(float);                  // 64KB
    const int smA = 3 * 128 * 64 * (int)sizeof(float);                  // 96KB
    const int smB = (128 * 128 + 64 * 128 + 256) * (int)sizeof(float);  // ~97KB
    cudaFuncSetAttribute(gemm128,    cudaFuncAttributeMaxDynamicSharedMemorySize, smG);
    cudaFuncSetAttribute(attn_score, cudaFuncAttributeMaxDynamicSharedMemorySize, smA);
    cudaFuncSetAttribute(attn_pv,    cudaFuncAttributeMaxDynamicSharedMemorySize, smB);

    dim3 gp(INNER / 128, M / 128);
    gemm128<<<gp, 512, smG>>>(fr, Wq, nullptr, pQ, M, INNER, DIM);
    gemm128<<<gp, 512, smG>>>(dt, Wk, nullptr, pK, M, INNER, DIM);
    gemm128<<<gp, 512, smG>>>(dt, Wv, nullptr, pV, M, INNER, DIM);

    attn_score<<<dim3(16, N_HEAD, BATCH), 256, smA>>>();
    attn_pv<<<dim3(16, N_HEAD, BATCH), 256, smB>>>();

    dim3 go(DIM / 128, M / 128);
    gemm128<<<go, 512, smG>>>(pO, Wo, bo, out, M, DIM, INNER);
}

// round 14
// speedup vs baseline: 1.1855x; 1.0140x over previous
#include <cuda_runtime.h>
#include <cstdint>

#define BATCH 2
#define SEQ 2048
#define DIM 512
#define INNER 512
#define N_HEAD 8
#define HEAD_DIM 64
#define ATT_T 1e-4f
#define SCALE_F 0.125f

typedef unsigned long long ull;
typedef unsigned u32;

// scratch (allocation-free rule: __device__ globals)
__device__ float g_Q[BATCH * SEQ * INNER];
__device__ float g_K[BATCH * SEQ * INNER];
__device__ float g_V[BATCH * SEQ * INNER];
__device__ float g_O[BATCH * SEQ * INNER];
__device__ float g_P[(size_t)BATCH * N_HEAD * SEQ * SEQ];   // exp(scores)
__device__ float g_Z[BATCH * N_HEAD * SEQ];

// ---------------- packed f32x2 helpers ---------------------------------
static __device__ __forceinline__ void fma2(ull& d, ull a, ull b) {
    asm("fma.rn.f32x2 %0, %1, %2, %0;" : "+l"(d) : "l"(a), "l"(b));
}
static __device__ __forceinline__ float psum(ull v) {
    u32 lo, hi;
    asm("mov.b64 {%0, %1}, %2;" : "=r"(lo), "=r"(hi) : "l"(v));
    return __uint_as_float(lo) + __uint_as_float(hi);
}
// quad-swizzled float4 store: logical quad (c>>2) -> physical (c>>2)^tag
static __device__ __forceinline__ void st_q4(float* base, int stride_f,
                                             int row, int c, int tag, float4 v) {
    *(float4*)&base[row * stride_f + (((c >> 2) ^ tag) << 2)] = v;
}

// ---------------------------------------------------------------------------
// gemm128: C[M,N] = A[M,K] @ B[K,N] (+bias). 512 thr, 128x128 tile, BK=64.
// As[m][64k] tag m>>3 (broadcast reads); Bs[n][64k] tag (n>>2)&15.
// Inner: LDS.128 (ulonglong2) quad loads, FFMA2.
// ---------------------------------------------------------------------------
__global__ void __launch_bounds__(512, 1) gemm128(
    const float* __restrict__ A, const float* __restrict__ B,
    const float* __restrict__ bias, float* __restrict__ C, int M, int N, int K)
{
    extern __shared__ float sm[];
    float* As = sm;              // 128 x 64
    float* Bs = sm + 128 * 64;   // 128 x 64 (B transposed)
    const int tid = threadIdx.x, tx = tid & 31, ty = tid >> 5;
    const int tx4 = tx << 2, ty8 = ty << 3;
    const int txt = tx & 15;
    const int bn = blockIdx.x * 128, bm = blockIdx.y * 128;

    ull acc2[8][4];
    #pragma unroll
    for (int i = 0; i < 8; i++)
        #pragma unroll
        for (int j = 0; j < 4; j++) acc2[i][j] = 0ull;

    for (int kc = 0; kc < K; kc += 64) {
        __syncthreads();
        #pragma unroll
        for (int i = 0; i < 4; i++) {
            int idx = tid + 512 * i, row = idx >> 4, c = (idx & 15) << 2;
            float4 v = *(const float4*)&A[(size_t)(bm + row) * K + kc + c];
            st_q4(As, 64, row, c, (row >> 3) & 15, v);
        }
        #pragma unroll
        for (int i = 0; i < 4; i++) {
            int idx = tid + 512 * i, k = idx >> 5, c = (idx & 31) << 2;
            float4 v = *(const float4*)&B[(size_t)(kc + k) * N + bn + c];
            float vv[4] = {v.x, v.y, v.z, v.w};
            #pragma unroll
            for (int j = 0; j < 4; j++) {
                int n = c + j;
                Bs[n * 64 + (((k >> 2) ^ ((n >> 2) & 15)) << 2) + (k & 3)] = vv[j];
            }
        }
        __syncthreads();
        #pragma unroll 4
        for (int dq = 0; dq < 16; dq++) {
            ulonglong2 a4[8], b4[4];
            int ao = ((dq ^ ty) & 15) << 2;
            int bo = ((dq ^ txt) & 15) << 2;
            #pragma unroll
            for (int i = 0; i < 8; i++)
                a4[i] = *(const ulonglong2*)&As[(ty8 + i) * 64 + ao];
            #pragma unroll
            for (int j = 0; j < 4; j++)
                b4[j] = *(const ulonglong2*)&Bs[(tx4 + j) * 64 + bo];
            #pragma unroll
            for (int i = 0; i < 8; i++)
                #pragma unroll
                for (int j = 0; j < 4; j++) {
                    fma2(acc2[i][j], a4[i].x, b4[j].x);
                    fma2(acc2[i][j], a4[i].y, b4[j].y);
                }
        }
    }
    #pragma unroll
    for (int i = 0; i < 8; i++) {
        int row = bm + ty8 + i, col = bn + tx4;
        float4 o = {psum(acc2[i][0]), psum(acc2[i][1]), psum(acc2[i][2]), psum(acc2[i][3])};
        if (bias) { o.x += bias[col]; o.y += bias[col+1]; o.z += bias[col+2]; o.w += bias[col+3]; }
        *(float4*)&C[(size_t)row * N + col] = o;
    }
}

// ---------------------------------------------------------------------------
// Pass A: P = exp(QK^T*scale) -> g_P, Z = row sums. 256 thr = 16(ty)x16(tx),
// 8x8 micro-tile, LDS.128 quad loads, K double-buffered.
// Qs/Ks [128][64], tag = row>>3 (Q reads broadcast on ty; K reads 16-across
// on tx with tag=tx -> conflict-free at crossbar floor).
// ---------------------------------------------------------------------------
static __device__ __forceinline__ void fill_tile_q(
    float* dst, const float* src, int tid, float scale)
{
    #pragma unroll
    for (int i = 0; i < 8; i++) {
        int idx = tid + 256 * i, row = idx >> 4, c = (idx & 15) << 2;
        float4 v = *(const float4*)&src[(size_t)row * INNER + c];
        v.x *= scale; v.y *= scale; v.z *= scale; v.w *= scale;
        st_q4(dst, 64, row, c, (row >> 3) & 15, v);
    }
}

__global__ void __launch_bounds__(256, 1) attn_score()
{
    extern __shared__ float sm[];
    float* Qs = sm;                                   // 128 x 64
    float* Kb0 = sm + 8192;
    float* Kb1 = sm + 16384;

    const int tid = threadIdx.x;
    const int tx = tid & 15, ty = tid >> 4;
    const int tx8 = tx << 3, ty8 = ty << 3;
    const int qt = blockIdx.x, h = blockIdx.y, b = blockIdx.z;

    const size_t baseQ = ((size_t)b * SEQ + qt * 128) * INNER + h * HEAD_DIM;
    const size_t baseK = ((size_t)b * SEQ) * INNER + h * HEAD_DIM;
    const size_t rowP = ((size_t)(b * N_HEAD + h) * SEQ + qt * 128);

    fill_tile_q(Qs, &g_Q[baseQ], tid, SCALE_F);
    fill_tile_q(Kb0, &g_K[baseK], tid, 1.f);

    float l[8];
    #pragma unroll
    for (int i = 0; i < 8; i++) l[i] = 0.f;

    for (int kt = 0; kt < 16; kt++) {
        __syncthreads();
        const float* Ks = (kt & 1) ? Kb1 : Kb0;

        ull acc2[8][8];
        #pragma unroll
        for (int i = 0; i < 8; i++)
            #pragma unroll
            for (int j = 0; j < 8; j++) acc2[i][j] = 0ull;

        #pragma unroll 4
        for (int dq = 0; dq < 16; dq++) {
            ulonglong2 q4[8];
            int qo = ((dq ^ ty) & 15) << 2;
            int ko = ((dq ^ tx) & 15) << 2;
            #pragma unroll
            for (int i = 0; i < 8; i++)
                q4[i] = *(const ulonglong2*)&Qs[(ty8 + i) * 64 + qo];
            // two halves of K to bound operand registers
            #pragma unroll
            for (int jh = 0; jh < 2; jh++) {
                ulonglong2 k4[4];
                #pragma unroll
                for (int j = 0; j < 4; j++)
                    k4[j] = *(const ulonglong2*)&Ks[(tx8 + jh * 4 + j) * 64 + ko];
                #pragma unroll
                for (int i = 0; i < 8; i++)
                    #pragma unroll
                    for (int j = 0; j < 4; j++) {
                        fma2(acc2[i][jh * 4 + j], q4[i].x, k4[j].x);
                        fma2(acc2[i][jh * 4 + j], q4[i].y, k4[j].y);
                    }
            }
        }

        // prefetch next K (overlaps epilogue)
        if (kt < 15)
            fill_tile_q((kt & 1) ? Kb0 : Kb1,
                        &g_K[baseK + (size_t)(kt + 1) * 128 * INNER], tid, 1.f);

        #pragma unroll
        for (int qi = 0; qi < 8; qi++) {
            float p[8];
            #pragma unroll
            for (int j = 0; j < 8; j++) p[j] = __expf(psum(acc2[qi][j]));
            l[qi] += ((p[0] + p[1]) + (p[2] + p[3])) + ((p[4] + p[5]) + (p[6] + p[7]));
            size_t ro = (rowP + ty8 + qi) * SEQ + kt * 128 + tx8;
            *(float4*)&g_P[ro] = make_float4(p[0], p[1], p[2], p[3]);
            *(float4*)&g_P[ro + 4] = make_float4(p[4], p[5], p[6], p[7]);
        }
    }

    #pragma unroll
    for (int qi = 0; qi < 8; qi++) {
        float v = l[qi];
        #pragma unroll
        for (int o = 1; o < 16; o <<= 1)
            v += __shfl_xor_sync(0xffffffffu, v, o);
        if (tx == 0)
            g_Z[(b * N_HEAD + h) * SEQ + qt * 128 + ty8 + qi] = v;
    }
}

// ---------------------------------------------------------------------------
// Pass B: w = relu(P - t*Z), O = (w @ V) / rowsum(w). 256 thr = 16x16, 8q x 4d.
// Ws[q][128] tag q>>3 (broadcast reads); Vs[d][128] tag (d>>2)&15 (16-across).
// LDS.128 quad loads; deferred wsum in registers.
// ---------------------------------------------------------------------------
__global__ void __launch_bounds__(256, 2) attn_pv()
{
    extern __shared__ float sm[];
    float* Ws = sm;                    // 128 x 128
    float* Vs = Ws + 128 * 128;        // 64 x 128 (V^T)
    float* wsumS = Vs + 64 * 128;      // 128
    float* thrS  = wsumS + 128;        // 128

    const int tid = threadIdx.x;
    const int tx = tid & 15, ty = tid >> 4;
    const int wid = tid >> 5, lane = tid & 31;
    const int tx4 = tx << 2, ty8 = ty << 3;
    const int qt = blockIdx.x, h = blockIdx.y, b = blockIdx.z;

    const size_t baseV = ((size_t)b * SEQ) * INNER + h * HEAD_DIM;
    const size_t baseO = ((size_t)b * SEQ + qt * 128) * INNER + h * HEAD_DIM;
    const size_t rowP  = ((size_t)(b * N_HEAD + h) * SEQ + qt * 128);
    const int    rowZ  = (b * N_HEAD + h) * SEQ + qt * 128;

    if (tid < 128) thrS[tid] = ATT_T * g_Z[rowZ + tid];

    float wpart[16];
    #pragma unroll
    for (int i = 0; i < 16; i++) wpart[i] = 0.f;

    ull oacc[8][4];
    #pragma unroll
    for (int i = 0; i < 8; i++)
        #pragma unroll
        for (int j = 0; j < 4; j++) oacc[i][j] = 0ull;

    for (int kt = 0; kt < 16; kt++) {
        __syncthreads();
        // fill Ws: w = relu(P - thr); row = 8i+wid, 32 quads/row, tag row>>3
        #pragma unroll
        for (int i = 0; i < 16; i++) {
            int idx = tid + 256 * i;
            int row = idx >> 5;
            int c   = (idx & 31) << 2;
            float4 p = *(const float4*)&g_P[(rowP + row) * SEQ + kt * 128 + c];
            float t = thrS[row];
            float4 w;
            w.x = fmaxf(p.x - t, 0.f); w.y = fmaxf(p.y - t, 0.f);
            w.z = fmaxf(p.z - t, 0.f); w.w = fmaxf(p.w - t, 0.f);
            wpart[i] += (w.x + w.y) + (w.z + w.w);
            *(float4*)&Ws[row * 128 + (((c >> 2) ^ ((row >> 3) & 15)) << 2)] = w;
        }
        // fill Vs (transpose), tag (d>>2)&15
        #pragma unroll
        for (int i = 0; i < 8; i++) {
            int idx = tid + 256 * i;
            int k   = idx >> 4;                 // 0..127
            int c   = (idx & 15) << 2;          // d
            float4 v = *(const float4*)&g_V[baseV + (size_t)(kt * 128 + k) * INNER + c];
            float vv[4] = {v.x, v.y, v.z, v.w};
            #pragma unroll
            for (int j = 0; j < 4; j++) {
                int d = c + j;
                Vs[d * 128 + (((k >> 2) ^ ((d >> 2) & 15)) << 2) + (k & 3)] = vv[j];
            }
        }
        __syncthreads();

        #pragma unroll 4
        for (int dq = 0; dq < 32; dq++) {
            ulonglong2 v4[4];
            int wo = (dq ^ ty) << 2;
            int vo = ((dq ^ tx) & 31) << 2;
            #pragma unroll
            for (int j = 0; j < 4; j++)
                v4[j] = *(const ulonglong2*)&Vs[(tx4 + j) * 128 + vo];
            #pragma unroll
            for (int ih = 0; ih < 2; ih++) {
                ulonglong2 w4[4];
                #pragma unroll
                for (int i = 0; i < 4; i++)
                    w4[i] = *(const ulonglong2*)&Ws[(ty8 + ih * 4 + i) * 128 + wo];
                #pragma unroll
                for (int i = 0; i < 4; i++)
                    #pragma unroll
                    for (int j = 0; j < 4; j++) {
                        fma2(oacc[ih * 4 + i][j], w4[i].x, v4[j].x);
                        fma2(oacc[ih * 4 + i][j], w4[i].y, v4[j].y);
                    }
            }
        }
    }

    __syncthreads();
    #pragma unroll
    for (int i = 0; i < 16; i++) {
        float s = wpart[i];
        #pragma unroll
        for (int o = 16; o > 0; o >>= 1)
            s += __shfl_xor_sync(0xffffffffu, s, o);
        if (lane == 0) wsumS[8 * i + wid] = s;
    }
    __syncthreads();

    #pragma unroll
    for (int qi = 0; qi < 8; qi++) {
        float inv = 1.f / wsumS[ty8 + qi];
        float4 ov = {psum(oacc[qi][0]) * inv, psum(oacc[qi][1]) * inv,
                     psum(oacc[qi][2]) * inv, psum(oacc[qi][3]) * inv};
        *(float4*)&g_O[baseO + (size_t)(ty8 + qi) * INNER + tx4] = ov;
    }
}

// ---------------------------------------------------------------------------
extern "C" void kernel_launch(void* const* d_in, const int* in_sizes, int n_in,
                              void* d_out, int out_size)
{
    const float* fr = (const float*)d_in[0];
    const float* dt = (const float*)d_in[1];
    const float* Wq = (const float*)d_in[2];
    const float* Wk = (const float*)d_in[3];
    const float* Wv = (const float*)d_in[4];
    const float* Wo = (const float*)d_in[5];
    const float* bo = (const float*)d_in[6];
    float* out = (float*)d_out;

    float *pQ, *pK, *pV, *pO;
    cudaGetSymbolAddress((void**)&pQ, g_Q);
    cudaGetSymbolAddress((void**)&pK, g_K);
    cudaGetSymbolAddress((void**)&pV, g_V);
    cudaGetSymbolAddress((void**)&pO, g_O);

    const int M = BATCH * SEQ;   // 4096

    const int smG = 128 * 64 * 2 * (int)sizeof(float);                  // 64KB
    const int smA = 3 * 128 * 64 * (int)sizeof(float);                  // 96KB
    const int smB = (128 * 128 + 64 * 128 + 256) * (int)sizeof(float);  // ~97KB
    cudaFuncSetAttribute(gemm128,    cudaFuncAttributeMaxDynamicSharedMemorySize, smG);
    cudaFuncSetAttribute(attn_score, cudaFuncAttributeMaxDynamicSharedMemorySize, smA);
    cudaFuncSetAttribute(attn_pv,    cudaFuncAttributeMaxDynamicSharedMemorySize, smB);

    dim3 gp(INNER / 128, M / 128);
    gemm128<<<gp, 512, smG>>>(fr, Wq, nullptr, pQ, M, INNER, DIM);
    gemm128<<<gp, 512, smG>>>(dt, Wk, nullptr, pK, M, INNER, DIM);
    gemm128<<<gp, 512, smG>>>(dt, Wv, nullptr, pV, M, INNER, DIM);

    attn_score<<<dim3(16, N_HEAD, BATCH), 256, smA>>>();
    attn_pv<<<dim3(16, N_HEAD, BATCH), 256, smB>>>();

    dim3 go(DIM / 128, M / 128);
    gemm128<<<go, 512, smG>>>(pO, Wo, bo, out, M, DIM, INNER);
}

// round 15
// speedup vs baseline: 1.2223x; 1.0310x over previous
#include <cuda_runtime.h>
#include <cstdint>

#define BATCH 2
#define SEQ 2048
#define DIM 512
#define INNER 512
#define N_HEAD 8
#define HEAD_DIM 64
#define ATT_T 1e-4f
#define SCALE_F 0.125f
#define LOG2E 1.4426950408889634f

typedef unsigned long long ull;
typedef unsigned u32;

// scratch (allocation-free rule: __device__ globals)
__device__ float g_Q[BATCH * SEQ * INNER];
__device__ float g_K[BATCH * SEQ * INNER];
__device__ float g_V[BATCH * SEQ * INNER];
__device__ float g_O[BATCH * SEQ * INNER];
__device__ float g_P[(size_t)BATCH * N_HEAD * SEQ * SEQ];   // exp(scores)
__device__ float g_Z[BATCH * N_HEAD * SEQ];

// ---------------- packed f32x2 helpers ---------------------------------
static __device__ __forceinline__ void fma2(ull& d, ull a, ull b) {
    asm("fma.rn.f32x2 %0, %1, %2, %0;" : "+l"(d) : "l"(a), "l"(b));
}
static __device__ __forceinline__ float psum(ull v) {
    u32 lo, hi;
    asm("mov.b64 {%0, %1}, %2;" : "=r"(lo), "=r"(hi) : "l"(v));
    return __uint_as_float(lo) + __uint_as_float(hi);
}
static __device__ __forceinline__ float ex2(float x) {
    float r;
    asm("ex2.approx.ftz.f32 %0, %1;" : "=f"(r) : "f"(x));
    return r;
}
// quad-swizzled float4 store: logical quad (c>>2) -> physical (c>>2)^tag
static __device__ __forceinline__ void st_q4(float* base, int stride_f,
                                             int row, int c, int tag, float4 v) {
    *(float4*)&base[row * stride_f + (((c >> 2) ^ tag) << 2)] = v;
}

// ---------------------------------------------------------------------------
// gemm body: C[M,N] = A[M,K] @ B[K,N] (+bias). 512 thr, 128x128 tile, BK=64.
// ---------------------------------------------------------------------------
static __device__ __forceinline__ void gemm_body(
    const float* __restrict__ A, const float* __restrict__ B,
    const float* __restrict__ bias, float* __restrict__ C,
    int M, int N, int K, float* sm, int bn, int bm)
{
    float* As = sm;              // 128 x 64
    float* Bs = sm + 128 * 64;   // 128 x 64 (B transposed)
    const int tid = threadIdx.x, tx = tid & 31, ty = tid >> 5;
    const int tx4 = tx << 2, ty8 = ty << 3;
    const int txt = tx & 15;

    ull acc2[8][4];
    #pragma unroll
    for (int i = 0; i < 8; i++)
        #pragma unroll
        for (int j = 0; j < 4; j++) acc2[i][j] = 0ull;

    for (int kc = 0; kc < K; kc += 64) {
        __syncthreads();
        #pragma unroll
        for (int i = 0; i < 4; i++) {
            int idx = tid + 512 * i, row = idx >> 4, c = (idx & 15) << 2;
            float4 v = *(const float4*)&A[(size_t)(bm + row) * K + kc + c];
            st_q4(As, 64, row, c, (row >> 3) & 15, v);
        }
        #pragma unroll
        for (int i = 0; i < 4; i++) {
            int idx = tid + 512 * i, k = idx >> 5, c = (idx & 31) << 2;
            float4 v = *(const float4*)&B[(size_t)(kc + k) * N + bn + c];
            float vv[4] = {v.x, v.y, v.z, v.w};
            #pragma unroll
            for (int j = 0; j < 4; j++) {
                int n = c + j;
                Bs[n * 64 + (((k >> 2) ^ ((n >> 2) & 15)) << 2) + (k & 3)] = vv[j];
            }
        }
        __syncthreads();
        #pragma unroll 4
        for (int dq = 0; dq < 16; dq++) {
            ulonglong2 a4[8], b4[4];
            int ao = ((dq ^ ty) & 15) << 2;
            int bo = ((dq ^ txt) & 15) << 2;
            #pragma unroll
            for (int i = 0; i < 8; i++)
                a4[i] = *(const ulonglong2*)&As[(ty8 + i) * 64 + ao];
            #pragma unroll
            for (int j = 0; j < 4; j++)
                b4[j] = *(const ulonglong2*)&Bs[(tx4 + j) * 64 + bo];
            #pragma unroll
            for (int i = 0; i < 8; i++)
                #pragma unroll
                for (int j = 0; j < 4; j++) {
                    fma2(acc2[i][j], a4[i].x, b4[j].x);
                    fma2(acc2[i][j], a4[i].y, b4[j].y);
                }
        }
    }
    #pragma unroll
    for (int i = 0; i < 8; i++) {
        int row = bm + ty8 + i, col = bn + tx4;
        float4 o = {psum(acc2[i][0]), psum(acc2[i][1]), psum(acc2[i][2]), psum(acc2[i][3])};
        if (bias) { o.x += bias[col]; o.y += bias[col+1]; o.z += bias[col+2]; o.w += bias[col+3]; }
        *(float4*)&C[(size_t)row * N + col] = o;
    }
}

__global__ void __launch_bounds__(512, 1) gemm128(
    const float* __restrict__ A, const float* __restrict__ B,
    const float* __restrict__ bias, float* __restrict__ C, int M, int N, int K)
{
    extern __shared__ float sm[];
    gemm_body(A, B, bias, C, M, N, K, sm, blockIdx.x * 128, blockIdx.y * 128);
}

// merged Q/K/V projection: grid.z selects operand set -> one big wave
__global__ void __launch_bounds__(512, 1) qkv_gemm(
    const float* __restrict__ fr, const float* __restrict__ dt,
    const float* __restrict__ Wq, const float* __restrict__ Wk,
    const float* __restrict__ Wv)
{
    extern __shared__ float sm[];
    const float* A;
    const float* B;
    float* C;
    if (blockIdx.z == 0)      { A = fr; B = Wq; C = g_Q; }
    else if (blockIdx.z == 1) { A = dt; B = Wk; C = g_K; }
    else                      { A = dt; B = Wv; C = g_V; }
    gemm_body(A, B, nullptr, C, BATCH * SEQ, INNER, DIM, sm,
              blockIdx.x * 128, blockIdx.y * 128);
}

// ---------------------------------------------------------------------------
// Pass A: P = exp2(Q'K^T) -> g_P  (Q pre-scaled by SCALE*log2e), Z row sums.
// 256 thr = 16(ty) x 16(tx), micro 8q x 4k, k-tile 64, 2 CTAs/SM.
// Qs[128][64] tag row>>3; K tiles [64][64] tag row>>2, double buffered.
// ---------------------------------------------------------------------------
__global__ void __launch_bounds__(256, 2) attn_score()
{
    extern __shared__ float sm[];
    float* Qs = sm;               // 128 x 64  (32KB)
    float* Kb0 = sm + 8192;       // 64 x 64   (16KB)
    float* Kb1 = sm + 12288;      // 64 x 64   (16KB)

    const int tid = threadIdx.x;
    const int tx = tid & 15, ty = tid >> 4;
    const int tx4 = tx << 2, ty8 = ty << 3;
    const int qt = blockIdx.x, h = blockIdx.y, b = blockIdx.z;

    const size_t baseQ = ((size_t)b * SEQ + qt * 128) * INNER + h * HEAD_DIM;
    const size_t baseK = ((size_t)b * SEQ) * INNER + h * HEAD_DIM;
    const size_t rowP = ((size_t)(b * N_HEAD + h) * SEQ + qt * 128);

    // fill Q (scaled so scores are already in log2 domain)
    #pragma unroll
    for (int i = 0; i < 8; i++) {
        int idx = tid + 256 * i, row = idx >> 4, c = (idx & 15) << 2;
        float4 v = *(const float4*)&g_Q[baseQ + (size_t)row * INNER + c];
        const float s = SCALE_F * LOG2E;
        v.x *= s; v.y *= s; v.z *= s; v.w *= s;
        st_q4(Qs, 64, row, c, (row >> 3) & 15, v);
    }
    // fill K tile 0 (64 rows)
    #pragma unroll
    for (int i = 0; i < 4; i++) {
        int idx = tid + 256 * i, row = idx >> 4, c = (idx & 15) << 2;
        float4 v = *(const float4*)&g_K[baseK + (size_t)row * INNER + c];
        st_q4(Kb0, 64, row, c, (row >> 2) & 15, v);
    }

    float l[8];
    #pragma unroll
    for (int i = 0; i < 8; i++) l[i] = 0.f;

    for (int kt = 0; kt < 32; kt++) {
        __syncthreads();
        const float* Ks = (kt & 1) ? Kb1 : Kb0;

        ull acc2[8][4];
        #pragma unroll
        for (int i = 0; i < 8; i++)
            #pragma unroll
            for (int j = 0; j < 4; j++) acc2[i][j] = 0ull;

        #pragma unroll 4
        for (int dq = 0; dq < 16; dq++) {
            ulonglong2 q4[8], k4[4];
            int qo = ((dq ^ ty) & 15) << 2;
            int ko = ((dq ^ tx) & 15) << 2;
            #pragma unroll
            for (int i = 0; i < 8; i++)
                q4[i] = *(const ulonglong2*)&Qs[(ty8 + i) * 64 + qo];
            #pragma unroll
            for (int j = 0; j < 4; j++)
                k4[j] = *(const ulonglong2*)&Ks[(tx4 + j) * 64 + ko];
            #pragma unroll
            for (int i = 0; i < 8; i++)
                #pragma unroll
                for (int j = 0; j < 4; j++) {
                    fma2(acc2[i][j], q4[i].x, k4[j].x);
                    fma2(acc2[i][j], q4[i].y, k4[j].y);
                }
        }

        // prefetch next K tile into the other buffer (overlaps epilogue)
        if (kt < 31) {
            float* Kn = (kt & 1) ? Kb0 : Kb1;
            const float* src = &g_K[baseK + (size_t)(kt + 1) * 64 * INNER];
            #pragma unroll
            for (int i = 0; i < 4; i++) {
                int idx = tid + 256 * i, row = idx >> 4, c = (idx & 15) << 2;
                float4 v = *(const float4*)&src[(size_t)row * INNER + c];
                st_q4(Kn, 64, row, c, (row >> 2) & 15, v);
            }
        }

        // epilogue: exp2 + store + Z accumulation
        #pragma unroll
        for (int qi = 0; qi < 8; qi++) {
            float4 p;
            p.x = ex2(psum(acc2[qi][0]));
            p.y = ex2(psum(acc2[qi][1]));
            p.z = ex2(psum(acc2[qi][2]));
            p.w = ex2(psum(acc2[qi][3]));
            l[qi] += (p.x + p.y) + (p.z + p.w);
            *(float4*)&g_P[(rowP + ty8 + qi) * SEQ + kt * 64 + tx4] = p;
        }
    }

    #pragma unroll
    for (int qi = 0; qi < 8; qi++) {
        float v = l[qi];
        #pragma unroll
        for (int o = 1; o < 16; o <<= 1)
            v += __shfl_xor_sync(0xffffffffu, v, o);
        if (tx == 0)
            g_Z[(b * N_HEAD + h) * SEQ + qt * 128 + ty8 + qi] = v;
    }
}

// ---------------------------------------------------------------------------
// Pass B: w = relu(P - t*Z), O = (w @ V) / rowsum(w). 256 thr = 16x16, 8q x 4d.
// Reverse kt order (L2 reuse of score's freshest P tiles). Deferred wsum.
// ---------------------------------------------------------------------------
__global__ void __launch_bounds__(256, 2) attn_pv()
{
    extern __shared__ float sm[];
    float* Ws = sm;                    // 128 x 128
    float* Vs = Ws + 128 * 128;        // 64 x 128 (V^T)
    float* wsumS = Vs + 64 * 128;      // 128
    float* thrS  = wsumS + 128;        // 128

    const int tid = threadIdx.x;
    const int tx = tid & 15, ty = tid >> 4;
    const int wid = tid >> 5, lane = tid & 31;
    const int tx4 = tx << 2, ty8 = ty << 3;
    const int qt = blockIdx.x, h = blockIdx.y, b = blockIdx.z;

    const size_t baseV = ((size_t)b * SEQ) * INNER + h * HEAD_DIM;
    const size_t baseO = ((size_t)b * SEQ + qt * 128) * INNER + h * HEAD_DIM;
    const size_t rowP  = ((size_t)(b * N_HEAD + h) * SEQ + qt * 128);
    const int    rowZ  = (b * N_HEAD + h) * SEQ + qt * 128;

    if (tid < 128) thrS[tid] = ATT_T * g_Z[rowZ + tid];

    float wpart[16];
    #pragma unroll
    for (int i = 0; i < 16; i++) wpart[i] = 0.f;

    ull oacc[8][4];
    #pragma unroll
    for (int i = 0; i < 8; i++)
        #pragma unroll
        for (int j = 0; j < 4; j++) oacc[i][j] = 0ull;

    for (int kr = 0; kr < 16; kr++) {
        const int kt = 15 - kr;
        __syncthreads();
        #pragma unroll
        for (int i = 0; i < 16; i++) {
            int idx = tid + 256 * i;
            int row = idx >> 5;
            int c   = (idx & 31) << 2;
            float4 p = *(const float4*)&g_P[(rowP + row) * SEQ + kt * 128 + c];
            float t = thrS[row];
            float4 w;
            w.x = fmaxf(p.x - t, 0.f); w.y = fmaxf(p.y - t, 0.f);
            w.z = fmaxf(p.z - t, 0.f); w.w = fmaxf(p.w - t, 0.f);
            wpart[i] += (w.x + w.y) + (w.z + w.w);
            *(float4*)&Ws[row * 128 + (((c >> 2) ^ ((row >> 3) & 15)) << 2)] = w;
        }
        #pragma unroll
        for (int i = 0; i < 8; i++) {
            int idx = tid + 256 * i;
            int k   = idx >> 4;
            int c   = (idx & 15) << 2;
            float4 v = *(const float4*)&g_V[baseV + (size_t)(kt * 128 + k) * INNER + c];
            float vv[4] = {v.x, v.y, v.z, v.w};
            #pragma unroll
            for (int j = 0; j < 4; j++) {
                int d = c + j;
                Vs[d * 128 + (((k >> 2) ^ ((d >> 2) & 15)) << 2) + (k & 3)] = vv[j];
            }
        }
        __syncthreads();

        #pragma unroll 4
        for (int dq = 0; dq < 32; dq++) {
            ulonglong2 v4[4];
            int wo = (dq ^ ty) << 2;
            int vo = ((dq ^ tx) & 31) << 2;
            #pragma unroll
            for (int j = 0; j < 4; j++)
                v4[j] = *(const ulonglong2*)&Vs[(tx4 + j) * 128 + vo];
            #pragma unroll
            for (int ih = 0; ih < 2; ih++) {
                ulonglong2 w4[4];
                #pragma unroll
                for (int i = 0; i < 4; i++)
                    w4[i] = *(const ulonglong2*)&Ws[(ty8 + ih * 4 + i) * 128 + wo];
                #pragma unroll
                for (int i = 0; i < 4; i++)
                    #pragma unroll
                    for (int j = 0; j < 4; j++) {
                        fma2(oacc[ih * 4 + i][j], w4[i].x, v4[j].x);
                        fma2(oacc[ih * 4 + i][j], w4[i].y, v4[j].y);
                    }
            }
        }
    }

    __syncthreads();
    #pragma unroll
    for (int i = 0; i < 16; i++) {
        float s = wpart[i];
        #pragma unroll
        for (int o = 16; o > 0; o >>= 1)
            s += __shfl_xor_sync(0xffffffffu, s, o);
        if (lane == 0) wsumS[8 * i + wid] = s;
    }
    __syncthreads();

    #pragma unroll
    for (int qi = 0; qi < 8; qi++) {
        float inv = 1.f / wsumS[ty8 + qi];
        float4 ov = {psum(oacc[qi][0]) * inv, psum(oacc[qi][1]) * inv,
                     psum(oacc[qi][2]) * inv, psum(oacc[qi][3]) * inv};
        *(float4*)&g_O[baseO + (size_t)(ty8 + qi) * INNER + tx4] = ov;
    }
}

// ---------------------------------------------------------------------------
extern "C" void kernel_launch(void* const* d_in, const int* in_sizes, int n_in,
                              void* d_out, int out_size)
{
    const float* fr = (const float*)d_in[0];
    const float* dt = (const float*)d_in[1];
    const float* Wq = (const float*)d_in[2];
    const float* Wk = (const float*)d_in[3];
    const float* Wv = (const float*)d_in[4];
    const float* Wo = (const float*)d_in[5];
    const float* bo = (const float*)d_in[6];
    float* out = (float*)d_out;

    float* pO;
    cudaGetSymbolAddress((void**)&pO, g_O);

    const int M = BATCH * SEQ;   // 4096

    const int smG = 128 * 64 * 2 * (int)sizeof(float);                  // 64KB
    const int smA = (128 * 64 + 2 * 64 * 64) * (int)sizeof(float);      // 64KB
    const int smB = (128 * 128 + 64 * 128 + 256) * (int)sizeof(float);  // ~97KB
    cudaFuncSetAttribute(gemm128,    cudaFuncAttributeMaxDynamicSharedMemorySize, smG);
    cudaFuncSetAttribute(qkv_gemm,   cudaFuncAttributeMaxDynamicSharedMemorySize, smG);
    cudaFuncSetAttribute(attn_score, cudaFuncAttributeMaxDynamicSharedMemorySize, smA);
    cudaFuncSetAttribute(attn_pv,    cudaFuncAttributeMaxDynamicSharedMemorySize, smB);

    qkv_gemm<<<dim3(INNER / 128, M / 128, 3), 512, smG>>>(fr, dt, Wq, Wk, Wv);

    attn_score<<<dim3(16, N_HEAD, BATCH), 256, smA>>>();
    attn_pv<<<dim3(16, N_HEAD, BATCH), 256, smB>>>();

    dim3 go(DIM / 128, M / 128);
    gemm128<<<go, 512, smG>>>(pO, Wo, bo, out, M, DIM, INNER);
}